// round 7
// baseline (speedup 1.0000x reference)
#include <cuda_runtime.h>
#include <cstdint>

// Problem: states [B=64, L=4096, D=256] f32; w [256] f32; bias scalar f32.
// out[b,l] = reverse_cumsum_l( dot(states[b,l,:], w) + bias )
//
// Single persistent kernel, one block per batch row:
//  - 1024 threads = 32 warps. Warp w handles rows {w, w+32, ...} (128 rows),
//    each row = 2 coalesced float4 loads/lane (__ldcs, stream-once) + warp
//    shuffle reduce. Lane 0 parks value (+bias) in smem.
//  - __syncthreads, then block-wide suffix scan of the 4096 smem values
//    (4 elems/thread, warp suffix-scan + cross-warp combine), write out
//    coalesced as float4.
// No second kernel, no grid-wide fences/atomics: dependency is block-local.

static constexpr int B = 64;
static constexpr int L = 4096;
static constexpr int D = 256;            // 64 float4 per row
static constexpr int T = 1024;           // threads per block
static constexpr int WARPS = T / 32;     // 32
static constexpr int ROWS_PER_WARP = L / WARPS;  // 128

__global__ void __launch_bounds__(1024, 1)
qvalue_kernel(const float4* __restrict__ states4,
              const float4* __restrict__ w4,
              const float*  __restrict__ bias,
              float* __restrict__ out)
{
    __shared__ float vals[L];            // 16 KB
    __shared__ float warp_tot[WARPS];
    __shared__ float warp_off[WARPS];

    const int b    = blockIdx.x;
    const int t    = threadIdx.x;
    const int lane = t & 31;
    const int wid  = t >> 5;

    // per-lane slice of w, loaded once
    const float4 w0 = __ldg(&w4[lane]);
    const float4 w1 = __ldg(&w4[lane + 32]);
    const float  bv = __ldg(bias);

    const float4* slab = states4 + (size_t)b * L * (D / 4);

    // ---- phase 1: 128 dot products per warp, 2 rows per iteration ----
    #pragma unroll 4
    for (int i = 0; i < ROWS_PER_WARP; i += 2) {
        const int l0 = wid + (i    ) * WARPS;
        const int l1 = wid + (i + 1) * WARPS;
        const float4* r0 = slab + (size_t)l0 * (D / 4);
        const float4* r1 = slab + (size_t)l1 * (D / 4);

        // 4 back-to-back streaming loads -> deep MLP
        float4 a0 = __ldcs(&r0[lane]);
        float4 a1 = __ldcs(&r0[lane + 32]);
        float4 c0 = __ldcs(&r1[lane]);
        float4 c1 = __ldcs(&r1[lane + 32]);

        float s0 = a0.x * w0.x + a0.y * w0.y + a0.z * w0.z + a0.w * w0.w
                 + a1.x * w1.x + a1.y * w1.y + a1.z * w1.z + a1.w * w1.w;
        float s1 = c0.x * w0.x + c0.y * w0.y + c0.z * w0.z + c0.w * w0.w
                 + c1.x * w1.x + c1.y * w1.y + c1.z * w1.z + c1.w * w1.w;

        #pragma unroll
        for (int off = 16; off > 0; off >>= 1) {
            s0 += __shfl_xor_sync(0xFFFFFFFFu, s0, off);
            s1 += __shfl_xor_sync(0xFFFFFFFFu, s1, off);
        }

        if (lane == 0) {
            vals[l0] = s0 + bv;
            vals[l1] = s1 + bv;
        }
    }
    __syncthreads();

    // ---- phase 2: block-wide reverse cumulative sum over vals[0..L) ----
    // thread t owns 4 contiguous elements [4t, 4t+4)
    float v0 = vals[4 * t + 0];
    float v1 = vals[4 * t + 1];
    float v2 = vals[4 * t + 2];
    float v3 = vals[4 * t + 3];
    float total = v0 + v1 + v2 + v3;

    // inclusive SUFFIX scan within warp: lane i -> sum over lanes >= i
    float s = total;
    #pragma unroll
    for (int off = 1; off < 32; off <<= 1) {
        float n = __shfl_down_sync(0xFFFFFFFFu, s, off);
        if (lane < 32 - off) s += n;
    }

    if (lane == 0) warp_tot[wid] = s;    // warp's full sum
    __syncthreads();

    if (wid == 0) {
        float ws = warp_tot[lane];
        float ss = ws;
        #pragma unroll
        for (int off = 1; off < 32; off <<= 1) {
            float n = __shfl_down_sync(0xFFFFFFFFu, ss, off);
            if (lane < 32 - off) ss += n;
        }
        warp_off[lane] = ss - ws;        // exclusive suffix of warp sums
    }
    __syncthreads();

    // exclusive suffix for this thread: warps after mine + lanes after me
    float offset = warp_off[wid] + (s - total);

    float q3 = offset + v3;
    float q2 = q3 + v2;
    float q1 = q2 + v1;
    float q0 = q1 + v0;

    reinterpret_cast<float4*>(out + (size_t)b * L)[t] =
        make_float4(q0, q1, q2, q3);
}

extern "C" void kernel_launch(void* const* d_in, const int* in_sizes, int n_in,
                              void* d_out, int out_size)
{
    const float4* states4 = (const float4*)d_in[0];
    const float4* w4      = (const float4*)d_in[1];
    const float*  bias    = (const float*)d_in[2];
    float* out = (float*)d_out;

    qvalue_kernel<<<B, T>>>(states4, w4, bias, out);
}